// round 4
// baseline (speedup 1.0000x reference)
#include <cuda_runtime.h>
#include <cstdint>
#include <cstddef>

// ============================================================================
// EGNN layer: h' = h + MLP_u([h, scatter_add(MLP_m([h_s, h_r, dist]))])
//
// Restructuring: layer-1 of the edge MLP is linear in the gathered features:
//   m_in @ W1^T = P[sender] + Q[receiver] + dist*w1c + b1,
//   P = h@W1[:, :D]^T, Q = h@W1[:, D:2D]^T   (node-level GEMMs, 3.3 GFLOP)
// Only layer-2 (26 GFLOP) runs per-edge, fused gather -> silu -> tf32 MMA
// -> silu -> atomic scatter.
//
// NOTE: edge_index is int32 on device (JAX default config downcasts int64).
//
// Graph-capture safety: kernel_launch contains ONLY kernel launches.
// Scratch buffers are __device__ globals referenced via selector codes.
// All SMEM static and < 48 KB.
// ============================================================================

#define DD 128
#define NMAX 50176  // >= N = 50000

__device__ __align__(16) float g_P[(size_t)NMAX * DD];
__device__ __align__(16) float g_Q[(size_t)NMAX * DD];
__device__ __align__(16) float g_agg[(size_t)NMAX * DD];
__device__ __align__(16) float g_u1[(size_t)NMAX * DD];

__device__ __forceinline__ float* resolve_buf(int code, const float* ext) {
    switch (code) {
        case 1: return g_P;
        case 2: return g_Q;
        case 3: return g_agg;
        case 4: return g_u1;
        default: return (float*)ext;
    }
}

__device__ __forceinline__ float silu_f(float x) {
    return __fdividef(x, 1.f + __expf(-x));
}
__device__ __forceinline__ float tf32r(float x) {
    uint32_t u;
    asm("cvt.rna.tf32.f32 %0, %1;" : "=r"(u) : "f"(x));
    return __uint_as_float(u);
}
__device__ __forceinline__ void mma8(float* c, const uint32_t* a, const uint32_t* b) {
    asm volatile(
        "mma.sync.aligned.m16n8k8.row.col.f32.tf32.tf32.f32 "
        "{%0,%1,%2,%3},{%4,%5,%6,%7},{%8,%9},{%0,%1,%2,%3};\n"
        : "+f"(c[0]), "+f"(c[1]), "+f"(c[2]), "+f"(c[3])
        : "r"(a[0]), "r"(a[1]), "r"(a[2]), "r"(a[3]), "r"(b[0]), "r"(b[1]));
}

// ============================================================================
// Node-level GEMM: out[M,128] = epi( sum_p A_p[M,128] @ B_p^T )
// B_p row-major [128, ldb_p]. mode 0: raw; 1: silu(acc+bias); 2: acc+bias+resid.
// 256 threads, BM=128, N=128, BK=32. Static SMEM 36 KB.
// ============================================================================
__global__ __launch_bounds__(256) void gemm_node(
    const float* __restrict__ A0e, int a0c,
    const float* __restrict__ B0, int ldb0,
    int a1c, const float* __restrict__ B1, int ldb1,
    const float* __restrict__ bias, const float* __restrict__ resid,
    float* __restrict__ oute, int outc, int M, int mode)
{
    __shared__ float As[128][36];
    __shared__ float Bs[128][36];
    int tid = threadIdx.x;
    int warp = tid >> 5, ln = tid & 31;
    int m0 = blockIdx.x * 128;

    const float* A0 = resolve_buf(a0c, A0e);
    const float* A1 = (a1c == 0) ? nullptr : resolve_buf(a1c, nullptr);
    float* out = resolve_buf(outc, oute);

    float acc[16][4];
#pragma unroll
    for (int i = 0; i < 16; ++i) {
        acc[i][0] = 0.f; acc[i][1] = 0.f; acc[i][2] = 0.f; acc[i][3] = 0.f;
    }

    for (int p = 0; p < 2; ++p) {
        const float* A = p ? A1 : A0;
        const float* B = p ? B1 : B0;
        int ldb = p ? ldb1 : ldb0;
        if (!A) continue;
        for (int k0 = 0; k0 < 128; k0 += 32) {
#pragma unroll
            for (int i = 0; i < 4; ++i) {
                int r = (tid >> 3) + i * 32;
                int c = (tid & 7) * 4;
                float4 v = make_float4(0.f, 0.f, 0.f, 0.f);
                int gr = m0 + r;
                if (gr < M) v = *(const float4*)(A + (size_t)gr * 128 + k0 + c);
                v.x = tf32r(v.x); v.y = tf32r(v.y); v.z = tf32r(v.z); v.w = tf32r(v.w);
                *(float4*)&As[r][c] = v;
            }
#pragma unroll
            for (int i = 0; i < 4; ++i) {
                int n = (tid >> 3) + i * 32;
                int c = (tid & 7) * 4;
                const float* bp = B + (size_t)n * ldb + k0 + c;
                Bs[n][c + 0] = tf32r(bp[0]);
                Bs[n][c + 1] = tf32r(bp[1]);
                Bs[n][c + 2] = tf32r(bp[2]);
                Bs[n][c + 3] = tf32r(bp[3]);
            }
            __syncthreads();

            int srow = warp * 16 + (ln >> 2);
            int scol = ln & 3;
#pragma unroll
            for (int kk = 0; kk < 4; ++kk) {
                uint32_t a[4];
                a[0] = __float_as_uint(As[srow][kk * 8 + scol]);
                a[1] = __float_as_uint(As[srow + 8][kk * 8 + scol]);
                a[2] = __float_as_uint(As[srow][kk * 8 + scol + 4]);
                a[3] = __float_as_uint(As[srow + 8][kk * 8 + scol + 4]);
#pragma unroll
                for (int nt = 0; nt < 16; ++nt) {
                    uint32_t b[2];
                    b[0] = __float_as_uint(Bs[nt * 8 + (ln >> 2)][kk * 8 + scol]);
                    b[1] = __float_as_uint(Bs[nt * 8 + (ln >> 2)][kk * 8 + scol + 4]);
                    mma8(acc[nt], a, b);
                }
            }
            __syncthreads();
        }
    }

    int r0 = m0 + warp * 16 + (ln >> 2);
    int c0 = (ln & 3) * 2;
#pragma unroll
    for (int nt = 0; nt < 16; ++nt) {
        int col = nt * 8 + c0;
#pragma unroll
        for (int h8 = 0; h8 < 2; ++h8) {
            int row = r0 + h8 * 8;
            if (row >= M) continue;
#pragma unroll
            for (int q = 0; q < 2; ++q) {
                float v = acc[nt][h8 * 2 + q];
                int cc = col + q;
                if (mode == 1)      v = silu_f(v + bias[cc]);
                else if (mode == 2) v = v + bias[cc] + resid[(size_t)row * 128 + cc];
                out[(size_t)row * 128 + cc] = v;
            }
        }
    }
}

// ============================================================================
// Edge kernel, 64 edges per block, 256 threads (8 warps split over N):
//   a = silu(P[s] + Q[r] + dist*w1c + b1)   -> SMEM [64][132] tf32
//   m = silu(a @ W2^T + b2)                 W2 in per-warp registers
//   atomicAdd(g_agg[r], m)
// ============================================================================
__global__ __launch_bounds__(256) void edge_kernel(
    const float* __restrict__ coords,
    const int* __restrict__ ei,     // int32! (JAX downcasts int64)
    const float* __restrict__ W1, const float* __restrict__ b1,
    const float* __restrict__ W2, const float* __restrict__ b2,
    int E)
{
    __shared__ float As[64][132];
    __shared__ int   s_sh[64];
    __shared__ int   r_sh[64];
    __shared__ float dist_sh[64];
    __shared__ float b1s[128];
    __shared__ float w1cs[128];

    int tid = threadIdx.x;
    int warp = tid >> 5, ln = tid & 31;
    int e0 = blockIdx.x * 64;

    // meta
    if (tid < 64) {
        int e = e0 + tid;
        int s = 0, r = -1;
        float d = 0.f;
        if (e < E) {
            s = ei[e];
            r = ei[(size_t)E + e];
            float dx = coords[s * 3 + 0] - coords[r * 3 + 0];
            float dy = coords[s * 3 + 1] - coords[r * 3 + 1];
            float dz = coords[s * 3 + 2] - coords[r * 3 + 2];
            d = sqrtf(dx * dx + dy * dy + dz * dz);
        }
        s_sh[tid] = s; r_sh[tid] = r; dist_sh[tid] = d;
    }
    if (tid < 128) {
        b1s[tid]  = b1[tid];
        w1cs[tid] = W1[(size_t)tid * 257 + 256];
    }

    // W2 fragments into registers (warp w owns cols [16w, 16w+16)), L2-resident
    float breg[2][16][2];
#pragma unroll
    for (int nt = 0; nt < 2; ++nt) {
        int n = warp * 16 + nt * 8 + (ln >> 2);
#pragma unroll
        for (int kk = 0; kk < 16; ++kk) {
            int k = kk * 8 + (ln & 3);
            breg[nt][kk][0] = tf32r(__ldg(W2 + (size_t)n * 128 + k));
            breg[nt][kk][1] = tf32r(__ldg(W2 + (size_t)n * 128 + k + 4));
        }
    }
    __syncthreads();

    // gather + layer-1 epilogue into As (tf32)
#pragma unroll
    for (int it = 0; it < 8; ++it) {
        int idx = tid + it * 256;
        int i = idx >> 5;
        int j = (idx & 31) * 4;
        int s = s_sh[i], r = r_sh[i];
        float4 o = make_float4(0.f, 0.f, 0.f, 0.f);
        if (r >= 0) {
            float d = dist_sh[i];
            float4 pv = *(const float4*)(g_P + (size_t)s * 128 + j);
            float4 qv = *(const float4*)(g_Q + (size_t)r * 128 + j);
            o.x = tf32r(silu_f(pv.x + qv.x + d * w1cs[j + 0] + b1s[j + 0]));
            o.y = tf32r(silu_f(pv.y + qv.y + d * w1cs[j + 1] + b1s[j + 1]));
            o.z = tf32r(silu_f(pv.z + qv.z + d * w1cs[j + 2] + b1s[j + 2]));
            o.w = tf32r(silu_f(pv.w + qv.w + d * w1cs[j + 3] + b1s[j + 3]));
        }
        *(float4*)&As[i][j] = o;
    }
    __syncthreads();

    // MMA: acc[mt][nt] covers rows [16mt,16mt+16) x cols [16w+8nt, +8)
    float acc[4][2][4];
#pragma unroll
    for (int mt = 0; mt < 4; ++mt)
#pragma unroll
        for (int nt = 0; nt < 2; ++nt) {
            acc[mt][nt][0] = 0.f; acc[mt][nt][1] = 0.f;
            acc[mt][nt][2] = 0.f; acc[mt][nt][3] = 0.f;
        }

#pragma unroll
    for (int kk = 0; kk < 16; ++kk) {
        int k = kk * 8 + (ln & 3);
#pragma unroll
        for (int mt = 0; mt < 4; ++mt) {
            uint32_t a[4];
            int rr = mt * 16 + (ln >> 2);
            a[0] = __float_as_uint(As[rr][k]);
            a[1] = __float_as_uint(As[rr + 8][k]);
            a[2] = __float_as_uint(As[rr][k + 4]);
            a[3] = __float_as_uint(As[rr + 8][k + 4]);
#pragma unroll
            for (int nt = 0; nt < 2; ++nt) {
                uint32_t b[2];
                b[0] = __float_as_uint(breg[nt][kk][0]);
                b[1] = __float_as_uint(breg[nt][kk][1]);
                mma8(acc[mt][nt], a, b);
            }
        }
    }

    // epilogue: silu + atomic scatter
    int c0 = (ln & 3) * 2;
#pragma unroll
    for (int mt = 0; mt < 4; ++mt) {
#pragma unroll
        for (int h8 = 0; h8 < 2; ++h8) {
            int rowi = mt * 16 + (ln >> 2) + h8 * 8;
            int r = r_sh[rowi];
            if (r < 0) continue;
            float* dst = g_agg + (size_t)r * 128;
#pragma unroll
            for (int nt = 0; nt < 2; ++nt) {
                int col = warp * 16 + nt * 8 + c0;
                float v0 = silu_f(acc[mt][nt][h8 * 2 + 0] + __ldg(b2 + col));
                float v1 = silu_f(acc[mt][nt][h8 * 2 + 1] + __ldg(b2 + col + 1));
                atomicAdd(dst + col, v0);
                atomicAdd(dst + col + 1, v1);
            }
        }
    }
}

__global__ void zero_agg(int n4) {
    int i = blockIdx.x * 256 + threadIdx.x;
    if (i < n4) ((float4*)g_agg)[i] = make_float4(0.f, 0.f, 0.f, 0.f);
}

// ============================================================================
// Host launch: kernel launches ONLY (graph-capture safe).
// ============================================================================
extern "C" void kernel_launch(void* const* d_in, const int* in_sizes, int n_in,
                              void* d_out, int out_size)
{
    const float* h_ptr  = (const float*)d_in[0];
    const float* coords = (const float*)d_in[1];
    const int*   ei     = (const int*)d_in[2];   // int32 on device
    const float* W1     = (const float*)d_in[3];
    const float* b1     = (const float*)d_in[4];
    const float* W2     = (const float*)d_in[5];
    const float* b2     = (const float*)d_in[6];
    const float* U1     = (const float*)d_in[7];
    const float* c1     = (const float*)d_in[8];
    const float* U2     = (const float*)d_in[9];
    const float* c2     = (const float*)d_in[10];

    int N = in_sizes[0] / 128;
    int E = in_sizes[2] / 2;
    int mt = (N + 127) / 128;

    // P = h @ W1[:, :128]^T ; Q = h @ W1[:, 128:256]^T  (W1 row stride 257)
    gemm_node<<<mt, 256>>>(h_ptr, 0, W1, 257, 0, nullptr, 0,
                           nullptr, nullptr, nullptr, 1, N, 0);
    gemm_node<<<mt, 256>>>(h_ptr, 0, W1 + 128, 257, 0, nullptr, 0,
                           nullptr, nullptr, nullptr, 2, N, 0);

    int n4 = N * 32;  // N*128/4
    zero_agg<<<(n4 + 255) / 256, 256>>>(n4);

    edge_kernel<<<(E + 63) / 64, 256>>>(coords, ei, W1, b1, W2, b2, E);

    // u1 = silu(h @ U1a^T + agg @ U1b^T + c1)
    gemm_node<<<mt, 256>>>(h_ptr, 0, U1, 256, 3, U1 + 128, 256,
                           c1, nullptr, nullptr, 4, N, 1);
    // out = h + u1 @ U2^T + c2
    gemm_node<<<mt, 256>>>(nullptr, 4, U2, 128, 0, nullptr, 0,
                           c2, h_ptr, (float*)d_out, 0, N, 2);
}

// round 6
// speedup vs baseline: 1.5212x; 1.5212x over previous
#include <cuda_runtime.h>
#include <cuda_fp16.h>
#include <cstdint>
#include <cstddef>

// ============================================================================
// EGNN layer: h' = h + MLP_u([h, scatter_add(MLP_m([h_s, h_r, dist]))])
//
// Layer-1 of the edge MLP is linear in gathered features -> node-level GEMMs
// P = h@W1a^T, Q = h@W1b^T. Edge kernel: gather -> silu -> fp16 MMA (W2 in
// registers) -> silu -> staged float4 atomic scatter.
// ============================================================================

#define DD 128
#define NMAX 50176  // >= N = 50000

__device__ __align__(16) float g_P[(size_t)NMAX * DD];
__device__ __align__(16) float g_Q[(size_t)NMAX * DD];
__device__ __align__(16) float g_agg[(size_t)NMAX * DD];
__device__ __align__(16) float g_u1[(size_t)NMAX * DD];

__device__ __forceinline__ float* resolve_buf(int code, const float* ext) {
    switch (code) {
        case 1: return g_P;
        case 2: return g_Q;
        case 3: return g_agg;
        case 4: return g_u1;
        default: return (float*)ext;
    }
}

// silu via single-MUFU tanh.approx: silu(x) = 0.5x(1 + tanh(x/2))
__device__ __forceinline__ float silu_f(float x) {
    float t;
    asm("tanh.approx.f32 %0, %1;" : "=f"(t) : "f"(0.5f * x));
    return 0.5f * x * (1.f + t);
}
__device__ __forceinline__ float tf32r(float x) {
    uint32_t u;
    asm("cvt.rna.tf32.f32 %0, %1;" : "=r"(u) : "f"(x));
    return __uint_as_float(u);
}
__device__ __forceinline__ void mma8(float* c, const uint32_t* a, const uint32_t* b) {
    asm volatile(
        "mma.sync.aligned.m16n8k8.row.col.f32.tf32.tf32.f32 "
        "{%0,%1,%2,%3},{%4,%5,%6,%7},{%8,%9},{%0,%1,%2,%3};\n"
        : "+f"(c[0]), "+f"(c[1]), "+f"(c[2]), "+f"(c[3])
        : "r"(a[0]), "r"(a[1]), "r"(a[2]), "r"(a[3]), "r"(b[0]), "r"(b[1]));
}
__device__ __forceinline__ void mma16(float* c, const uint32_t* a, const uint32_t* b) {
    asm volatile(
        "mma.sync.aligned.m16n8k16.row.col.f32.f16.f16.f32 "
        "{%0,%1,%2,%3},{%4,%5,%6,%7},{%8,%9},{%0,%1,%2,%3};\n"
        : "+f"(c[0]), "+f"(c[1]), "+f"(c[2]), "+f"(c[3])
        : "r"(a[0]), "r"(a[1]), "r"(a[2]), "r"(a[3]), "r"(b[0]), "r"(b[1]));
}

// ============================================================================
// Node-level GEMM (tf32): out[M,128] = epi( sum_p A_p[M,128] @ B_p^T )
// mode 0: raw; 1: silu(acc+bias); 2: acc+bias+resid.
// ============================================================================
__global__ __launch_bounds__(256) void gemm_node(
    const float* __restrict__ A0e, int a0c,
    const float* __restrict__ B0, int ldb0,
    int a1c, const float* __restrict__ B1, int ldb1,
    const float* __restrict__ bias, const float* __restrict__ resid,
    float* __restrict__ oute, int outc, int M, int mode)
{
    __shared__ float As[128][36];
    __shared__ float Bs[128][36];
    int tid = threadIdx.x;
    int warp = tid >> 5, ln = tid & 31;
    int m0 = blockIdx.x * 128;

    const float* A0 = resolve_buf(a0c, A0e);
    const float* A1 = (a1c == 0) ? nullptr : resolve_buf(a1c, nullptr);
    float* out = resolve_buf(outc, oute);

    float acc[16][4];
#pragma unroll
    for (int i = 0; i < 16; ++i) {
        acc[i][0] = 0.f; acc[i][1] = 0.f; acc[i][2] = 0.f; acc[i][3] = 0.f;
    }

    for (int p = 0; p < 2; ++p) {
        const float* A = p ? A1 : A0;
        const float* B = p ? B1 : B0;
        int ldb = p ? ldb1 : ldb0;
        if (!A) continue;
        for (int k0 = 0; k0 < 128; k0 += 32) {
#pragma unroll
            for (int i = 0; i < 4; ++i) {
                int r = (tid >> 3) + i * 32;
                int c = (tid & 7) * 4;
                float4 v = make_float4(0.f, 0.f, 0.f, 0.f);
                int gr = m0 + r;
                if (gr < M) v = *(const float4*)(A + (size_t)gr * 128 + k0 + c);
                v.x = tf32r(v.x); v.y = tf32r(v.y); v.z = tf32r(v.z); v.w = tf32r(v.w);
                *(float4*)&As[r][c] = v;
            }
#pragma unroll
            for (int i = 0; i < 4; ++i) {
                int n = (tid >> 3) + i * 32;
                int c = (tid & 7) * 4;
                const float* bp = B + (size_t)n * ldb + k0 + c;
                Bs[n][c + 0] = tf32r(bp[0]);
                Bs[n][c + 1] = tf32r(bp[1]);
                Bs[n][c + 2] = tf32r(bp[2]);
                Bs[n][c + 3] = tf32r(bp[3]);
            }
            __syncthreads();

            int srow = warp * 16 + (ln >> 2);
            int scol = ln & 3;
#pragma unroll
            for (int kk = 0; kk < 4; ++kk) {
                uint32_t a[4];
                a[0] = __float_as_uint(As[srow][kk * 8 + scol]);
                a[1] = __float_as_uint(As[srow + 8][kk * 8 + scol]);
                a[2] = __float_as_uint(As[srow][kk * 8 + scol + 4]);
                a[3] = __float_as_uint(As[srow + 8][kk * 8 + scol + 4]);
#pragma unroll
                for (int nt = 0; nt < 16; ++nt) {
                    uint32_t b[2];
                    b[0] = __float_as_uint(Bs[nt * 8 + (ln >> 2)][kk * 8 + scol]);
                    b[1] = __float_as_uint(Bs[nt * 8 + (ln >> 2)][kk * 8 + scol + 4]);
                    mma8(acc[nt], a, b);
                }
            }
            __syncthreads();
        }
    }

    int r0 = m0 + warp * 16 + (ln >> 2);
    int c0 = (ln & 3) * 2;
#pragma unroll
    for (int nt = 0; nt < 16; ++nt) {
        int col = nt * 8 + c0;
#pragma unroll
        for (int h8 = 0; h8 < 2; ++h8) {
            int row = r0 + h8 * 8;
            if (row >= M) continue;
#pragma unroll
            for (int q = 0; q < 2; ++q) {
                float v = acc[nt][h8 * 2 + q];
                int cc = col + q;
                if (mode == 1)      v = silu_f(v + bias[cc]);
                else if (mode == 2) v = v + bias[cc] + resid[(size_t)row * 128 + cc];
                out[(size_t)row * 128 + cc] = v;
            }
        }
    }
}

// ============================================================================
// Edge kernel v2: 64 edges/block, 256 threads, fp16 MMA m16n8k16.
//   a = silu(P[s]+Q[r]+d*w1c+b1) -> half As[64][136] (in buf)
//   m = silu(a @ W2^T + b2)      -> float Ms[64][132] (buf reused)
//   atomicAdd float4 into g_agg, warp-per-row (coalesced vector RED)
// ============================================================================
#define AS_LD 136   // half stride (68 words -> conflict-free frag loads)
#define MS_LD 132   // float stride

__global__ __launch_bounds__(256) void edge_kernel(
    const float* __restrict__ coords,
    const int* __restrict__ ei,     // int32 (JAX downcasts int64)
    const float* __restrict__ W1, const float* __restrict__ b1,
    const float* __restrict__ W2, const float* __restrict__ b2,
    int E)
{
    __shared__ __align__(16) char buf[64 * MS_LD * 4];  // 33792 B, aliased
    __shared__ int   s_sh[64];
    __shared__ int   r_sh[64];
    __shared__ float dist_sh[64];
    __shared__ float b1s[128];
    __shared__ float w1cs[128];
    __shared__ float b2s[128];

    half  (*As)[AS_LD] = (half(*)[AS_LD])buf;
    float (*Ms)[MS_LD] = (float(*)[MS_LD])buf;

    int tid = threadIdx.x;
    int warp = tid >> 5, ln = tid & 31;
    int e0 = blockIdx.x * 64;

    // meta
    if (tid < 64) {
        int e = e0 + tid;
        int s = 0, r = -1;
        float d = 0.f;
        if (e < E) {
            s = ei[e];
            r = ei[(size_t)E + e];
            float dx = coords[s * 3 + 0] - coords[r * 3 + 0];
            float dy = coords[s * 3 + 1] - coords[r * 3 + 1];
            float dz = coords[s * 3 + 2] - coords[r * 3 + 2];
            d = sqrtf(dx * dx + dy * dy + dz * dz);
        }
        s_sh[tid] = s; r_sh[tid] = r; dist_sh[tid] = d;
    }
    if (tid < 128) {
        b1s[tid]  = b1[tid];
        w1cs[tid] = W1[(size_t)tid * 257 + 256];
        b2s[tid]  = b2[tid];
    }

    // W2 -> per-warp fp16 register fragments. warp w owns cols [16w,16w+16).
    uint32_t breg[2][8][2];
#pragma unroll
    for (int nt = 0; nt < 2; ++nt) {
        int n = warp * 16 + nt * 8 + (ln >> 2);
#pragma unroll
        for (int kc = 0; kc < 8; ++kc) {
            int k0 = kc * 16 + (ln & 3) * 2;
            float2 lo = *(const float2*)(W2 + (size_t)n * 128 + k0);
            float2 hi = *(const float2*)(W2 + (size_t)n * 128 + k0 + 8);
            __half2 hlo = __floats2half2_rn(lo.x, lo.y);
            __half2 hhi = __floats2half2_rn(hi.x, hi.y);
            breg[nt][kc][0] = *(uint32_t*)&hlo;
            breg[nt][kc][1] = *(uint32_t*)&hhi;
        }
    }
    __syncthreads();

    // gather + layer-1 + silu -> As (fp16)
#pragma unroll
    for (int it = 0; it < 8; ++it) {
        int idx = tid + it * 256;
        int i = idx >> 5;
        int j = (idx & 31) * 4;
        int s = s_sh[i], r = r_sh[i];
        float4 o = make_float4(0.f, 0.f, 0.f, 0.f);
        if (r >= 0) {
            float d = dist_sh[i];
            float4 pv = *(const float4*)(g_P + (size_t)s * 128 + j);
            float4 qv = *(const float4*)(g_Q + (size_t)r * 128 + j);
            o.x = silu_f(pv.x + qv.x + d * w1cs[j + 0] + b1s[j + 0]);
            o.y = silu_f(pv.y + qv.y + d * w1cs[j + 1] + b1s[j + 1]);
            o.z = silu_f(pv.z + qv.z + d * w1cs[j + 2] + b1s[j + 2]);
            o.w = silu_f(pv.w + qv.w + d * w1cs[j + 3] + b1s[j + 3]);
        }
        __half2 h0 = __floats2half2_rn(o.x, o.y);
        __half2 h1 = __floats2half2_rn(o.z, o.w);
        uint2 pk = make_uint2(*(uint32_t*)&h0, *(uint32_t*)&h1);
        *(uint2*)&As[i][j] = pk;
    }
    __syncthreads();

    // MMA: acc[mt][nt] = rows [16mt,16mt+16) x cols [16w+8nt,+8), K=128
    float acc[4][2][4];
#pragma unroll
    for (int mt = 0; mt < 4; ++mt)
#pragma unroll
        for (int nt = 0; nt < 2; ++nt) {
            acc[mt][nt][0] = 0.f; acc[mt][nt][1] = 0.f;
            acc[mt][nt][2] = 0.f; acc[mt][nt][3] = 0.f;
        }

#pragma unroll
    for (int kc = 0; kc < 8; ++kc) {
        int k0 = kc * 16 + (ln & 3) * 2;  // half index within row
#pragma unroll
        for (int mt = 0; mt < 4; ++mt) {
            int rr = mt * 16 + (ln >> 2);
            uint32_t a[4];
            a[0] = *(const uint32_t*)&As[rr][k0];
            a[1] = *(const uint32_t*)&As[rr + 8][k0];
            a[2] = *(const uint32_t*)&As[rr][k0 + 8];
            a[3] = *(const uint32_t*)&As[rr + 8][k0 + 8];
#pragma unroll
            for (int nt = 0; nt < 2; ++nt)
                mma16(acc[mt][nt], a, breg[nt][kc]);
        }
    }
    __syncthreads();  // As reads done; buf becomes Ms

    // stage m = silu(acc + b2) into Ms
    int c0 = (ln & 3) * 2;
#pragma unroll
    for (int mt = 0; mt < 4; ++mt) {
#pragma unroll
        for (int h8 = 0; h8 < 2; ++h8) {
            int rowi = mt * 16 + (ln >> 2) + h8 * 8;
#pragma unroll
            for (int nt = 0; nt < 2; ++nt) {
                int col = warp * 16 + nt * 8 + c0;
                float2 v;
                v.x = silu_f(acc[mt][nt][h8 * 2 + 0] + b2s[col]);
                v.y = silu_f(acc[mt][nt][h8 * 2 + 1] + b2s[col + 1]);
                *(float2*)&Ms[rowi][col] = v;
            }
        }
    }
    __syncthreads();

    // scatter: warp w -> rows [8w, 8w+8), float4 vector atomics (coalesced)
#pragma unroll
    for (int rr = 0; rr < 8; ++rr) {
        int row = warp * 8 + rr;
        int r = r_sh[row];
        if (r < 0) continue;
        float4 v = *(const float4*)&Ms[row][ln * 4];
        atomicAdd((float4*)(g_agg + (size_t)r * 128 + ln * 4), v);
    }
}

__global__ void zero_agg(int n4) {
    int i = blockIdx.x * 256 + threadIdx.x;
    if (i < n4) ((float4*)g_agg)[i] = make_float4(0.f, 0.f, 0.f, 0.f);
}

// ============================================================================
// Host launch: kernel launches ONLY (graph-capture safe).
// ============================================================================
extern "C" void kernel_launch(void* const* d_in, const int* in_sizes, int n_in,
                              void* d_out, int out_size)
{
    const float* h_ptr  = (const float*)d_in[0];
    const float* coords = (const float*)d_in[1];
    const int*   ei     = (const int*)d_in[2];
    const float* W1     = (const float*)d_in[3];
    const float* b1     = (const float*)d_in[4];
    const float* W2     = (const float*)d_in[5];
    const float* b2     = (const float*)d_in[6];
    const float* U1     = (const float*)d_in[7];
    const float* c1     = (const float*)d_in[8];
    const float* U2     = (const float*)d_in[9];
    const float* c2     = (const float*)d_in[10];

    int N = in_sizes[0] / 128;
    int E = in_sizes[2] / 2;
    int mt = (N + 127) / 128;

    gemm_node<<<mt, 256>>>(h_ptr, 0, W1, 257, 0, nullptr, 0,
                           nullptr, nullptr, nullptr, 1, N, 0);
    gemm_node<<<mt, 256>>>(h_ptr, 0, W1 + 128, 257, 0, nullptr, 0,
                           nullptr, nullptr, nullptr, 2, N, 0);

    int n4 = N * 32;
    zero_agg<<<(n4 + 255) / 256, 256>>>(n4);

    edge_kernel<<<(E + 63) / 64, 256>>>(coords, ei, W1, b1, W2, b2, E);

    gemm_node<<<mt, 256>>>(h_ptr, 0, U1, 256, 3, U1 + 128, 256,
                           c1, nullptr, nullptr, 4, N, 1);
    gemm_node<<<mt, 256>>>(nullptr, 4, U2, 128, 0, nullptr, 0,
                           c2, h_ptr, (float*)d_out, 0, N, 2);
}